// round 2
// baseline (speedup 1.0000x reference)
#include <cuda_runtime.h>

#define SEQ 8192
#define DIM 512
#define DK  64
#define BM  64
#define BN  128

// Scratch for projected Q/K/V (allocation-free: device globals).
__device__ float g_Q[SEQ * DK];
__device__ float g_K[SEQ * DK];
__device__ float g_V[SEQ * DK];

// ---------------------------------------------------------------------------
// Kernel 1: fused QKV projection.  C = x @ W  for W in {Wq, Wk, Wv} (blockIdx.y)
// Block tile: 64 rows x 64 cols, K-tiles of 64. 256 threads, 4x4 microtile.
// ---------------------------------------------------------------------------
__global__ __launch_bounds__(256, 1) void qkv_kernel(
    const float* __restrict__ x,
    const float* __restrict__ Wq,
    const float* __restrict__ Wk,
    const float* __restrict__ Wv)
{
    __shared__ float xs[64][68];   // xs[k][m]  (transposed x tile)
    __shared__ float ws[64][68];   // ws[k][n]

    const float* W;
    float* C;
    if (blockIdx.y == 0)      { W = Wq; C = g_Q; }
    else if (blockIdx.y == 1) { W = Wk; C = g_K; }
    else                      { W = Wv; C = g_V; }

    const int tid = threadIdx.x;
    const int tx = tid & 15;        // col group (4 cols)
    const int ty = tid >> 4;        // row group (4 rows)
    const int m0 = blockIdx.x * 64;

    float acc[4][4] = {};

    for (int kt = 0; kt < DIM; kt += 64) {
        // Load x tile (64 rows x 64 k), store transposed into xs[k][m].
        #pragma unroll
        for (int i = 0; i < 4; i++) {
            int f = i * 256 + tid;             // 1024 float4
            int row = f >> 4;
            int k4  = f & 15;
            float4 v = *(const float4*)(x + (size_t)(m0 + row) * DIM + kt + k4 * 4);
            xs[k4 * 4 + 0][row] = v.x;
            xs[k4 * 4 + 1][row] = v.y;
            xs[k4 * 4 + 2][row] = v.z;
            xs[k4 * 4 + 3][row] = v.w;
        }
        // Load W tile (64 k x 64 n) natural layout.
        #pragma unroll
        for (int i = 0; i < 4; i++) {
            int f = i * 256 + tid;
            int k  = f >> 4;
            int n4 = f & 15;
            *(float4*)&ws[k][n4 * 4] =
                *(const float4*)(W + (size_t)(kt + k) * DK + n4 * 4);
        }
        __syncthreads();

        #pragma unroll 16
        for (int k = 0; k < 64; k++) {
            float4 a = *(float4*)&xs[k][ty * 4];
            float4 b = *(float4*)&ws[k][tx * 4];
            float av[4] = {a.x, a.y, a.z, a.w};
            float bv[4] = {b.x, b.y, b.z, b.w};
            #pragma unroll
            for (int r = 0; r < 4; r++)
                #pragma unroll
                for (int c = 0; c < 4; c++)
                    acc[r][c] = fmaf(av[r], bv[c], acc[r][c]);
        }
        __syncthreads();
    }

    #pragma unroll
    for (int r = 0; r < 4; r++) {
        float4 v = make_float4(acc[r][0], acc[r][1], acc[r][2], acc[r][3]);
        *(float4*)(C + (size_t)(m0 + ty * 4 + r) * DK + tx * 4) = v;
    }
}

// ---------------------------------------------------------------------------
// Kernel 2: flash attention, fp32.
// Block: 64 queries. Stream KV in tiles of 128. Online softmax (m,l in regs,
// replicated across the 16-lane row group via width-16 shuffles).
// Thread map (both GEMMs): rows ty*4..+3. S cols: {tx*4..+3, 64+tx*4..+3}.
// O cols: tx*4..+3.
// ---------------------------------------------------------------------------
__global__ __launch_bounds__(256, 1) void flash_kernel(float* __restrict__ out)
{
    extern __shared__ float smem[];
    float (*Qs)[68]  = (float(*)[68])(smem);                              // 64 x 68
    float (*Ks)[132] = (float(*)[132])(smem + 64 * 68);                   // 64 x 132
    float (*Vs)[68]  = (float(*)[68])(smem + 64 * 68 + 64 * 132);         // 128 x 68
    float (*Ps)[68]  = (float(*)[68])(smem + 64 * 68 + 64 * 132 + 128 * 68); // 128 x 68

    const int tid = threadIdx.x;
    const int tx = tid & 15;
    const int ty = tid >> 4;
    const int m0 = blockIdx.x * BM;

    // Load Q tile, transposed to Qs[d][m], folding in the 1/sqrt(64) scale.
    #pragma unroll
    for (int i = 0; i < 4; i++) {
        int f = i * 256 + tid;
        int row = f >> 4;
        int d4  = f & 15;
        float4 v = *(const float4*)(g_Q + (size_t)(m0 + row) * DK + d4 * 4);
        Qs[d4 * 4 + 0][row] = v.x * 0.125f;
        Qs[d4 * 4 + 1][row] = v.y * 0.125f;
        Qs[d4 * 4 + 2][row] = v.z * 0.125f;
        Qs[d4 * 4 + 3][row] = v.w * 0.125f;
    }

    float O[4][4] = {};
    float mrow[4], lrow[4];
    #pragma unroll
    for (int r = 0; r < 4; r++) { mrow[r] = -1e30f; lrow[r] = 0.0f; }

    for (int t = 0; t < SEQ / BN; t++) {
        const int n0 = t * BN;

        // K tile -> Ks[d][n] (transposed).
        #pragma unroll
        for (int i = 0; i < 8; i++) {
            int f = i * 256 + tid;       // 2048 float4
            int row = f >> 4;            // 0..127
            int d4  = f & 15;
            float4 v = *(const float4*)(g_K + (size_t)(n0 + row) * DK + d4 * 4);
            Ks[d4 * 4 + 0][row] = v.x;
            Ks[d4 * 4 + 1][row] = v.y;
            Ks[d4 * 4 + 2][row] = v.z;
            Ks[d4 * 4 + 3][row] = v.w;
        }
        // V tile -> Vs[j][c] (natural).
        #pragma unroll
        for (int i = 0; i < 8; i++) {
            int f = i * 256 + tid;
            int j  = f >> 4;
            int c4 = f & 15;
            *(float4*)&Vs[j][c4 * 4] =
                *(const float4*)(g_V + (size_t)(n0 + j) * DK + c4 * 4);
        }
        __syncthreads();

        // S = (Q/8) @ K^T  (64x128 block tile; 4x8 per thread)
        float s[4][8] = {};
        #pragma unroll 8
        for (int d = 0; d < 64; d++) {
            float4 a  = *(float4*)&Qs[d][ty * 4];
            float4 b0 = *(float4*)&Ks[d][tx * 4];
            float4 b1 = *(float4*)&Ks[d][64 + tx * 4];
            float av[4] = {a.x, a.y, a.z, a.w};
            float bv[8] = {b0.x, b0.y, b0.z, b0.w, b1.x, b1.y, b1.z, b1.w};
            #pragma unroll
            for (int r = 0; r < 4; r++)
                #pragma unroll
                for (int c = 0; c < 8; c++)
                    s[r][c] = fmaf(av[r], bv[c], s[r][c]);
        }

        // Online softmax update per row.
        #pragma unroll
        for (int r = 0; r < 4; r++) {
            float mt = s[r][0];
            #pragma unroll
            for (int c = 1; c < 8; c++) mt = fmaxf(mt, s[r][c]);
            #pragma unroll
            for (int off = 8; off; off >>= 1)
                mt = fmaxf(mt, __shfl_xor_sync(0xffffffffu, mt, off, 16));

            float mn    = fmaxf(mrow[r], mt);
            float alpha = __expf(mrow[r] - mn);
            mrow[r] = mn;

            float rs = 0.0f;
            #pragma unroll
            for (int c = 0; c < 8; c++) {
                s[r][c] = __expf(s[r][c] - mn);
                rs += s[r][c];
            }
            #pragma unroll
            for (int off = 8; off; off >>= 1)
                rs += __shfl_xor_sync(0xffffffffu, rs, off, 16);

            lrow[r] = lrow[r] * alpha + rs;
            #pragma unroll
            for (int c = 0; c < 4; c++) O[r][c] *= alpha;
        }

        // Store P transposed: Ps[j][m] so PV reads are float4 along m.
        #pragma unroll
        for (int c = 0; c < 8; c++) {
            int col = (c < 4) ? (tx * 4 + c) : (64 + tx * 4 + (c - 4));
            float4 v = make_float4(s[0][c], s[1][c], s[2][c], s[3][c]);
            *(float4*)&Ps[col][ty * 4] = v;
        }
        __syncthreads();

        // O += P @ V  (64x64 block tile; 4x4 per thread, k = 128)
        #pragma unroll 8
        for (int j = 0; j < BN; j++) {
            float4 a = *(float4*)&Ps[j][ty * 4];
            float4 b = *(float4*)&Vs[j][tx * 4];
            float av[4] = {a.x, a.y, a.z, a.w};
            float bv[4] = {b.x, b.y, b.z, b.w};
            #pragma unroll
            for (int r = 0; r < 4; r++)
                #pragma unroll
                for (int c = 0; c < 4; c++)
                    O[r][c] = fmaf(av[r], bv[c], O[r][c]);
        }
        __syncthreads();
    }

    #pragma unroll
    for (int r = 0; r < 4; r++) {
        float inv = 1.0f / lrow[r];
        float4 v = make_float4(O[r][0] * inv, O[r][1] * inv,
                               O[r][2] * inv, O[r][3] * inv);
        *(float4*)(out + (size_t)(m0 + ty * 4 + r) * DK + tx * 4) = v;
    }
}

// ---------------------------------------------------------------------------
// Launch
// ---------------------------------------------------------------------------
extern "C" void kernel_launch(void* const* d_in, const int* in_sizes, int n_in,
                              void* d_out, int out_size)
{
    const float* x  = (const float*)d_in[0];
    const float* Wq = (const float*)d_in[1];
    const float* Wk = (const float*)d_in[2];
    const float* Wv = (const float*)d_in[3];
    float* out = (float*)d_out;

    dim3 g1(SEQ / 64, 3);
    qkv_kernel<<<g1, 256>>>(x, Wq, Wk, Wv);

    const int smem_bytes = (64 * 68 + 64 * 132 + 128 * 68 + 128 * 68) * 4; // 120832
    cudaFuncSetAttribute(flash_kernel,
                         cudaFuncAttributeMaxDynamicSharedMemorySize, smem_bytes);
    flash_kernel<<<SEQ / BM, 256, smem_bytes>>>(out);
}

// round 5
// speedup vs baseline: 2.8791x; 2.8791x over previous
#include <cuda_runtime.h>
#include <cuda_fp16.h>
#include <cstdint>

#define SEQ 8192
#define DIM 512
#define DK  64
#define DV  64
#define BM  128
#define BN  128
#define NSPLIT 2
#define KV_PER (SEQ/NSPLIT)
#define TILES  (KV_PER/BN)

// smem row strides (bytes), padded for ldmatrix bank behavior
#define KSTRIDE 160            // 64 halves (128B) + 32B pad
#define VSTRIDE 272            // 128 halves (256B) + 16B pad
#define K_TILE_B (128 * KSTRIDE)   // 20480
#define V_TILE_B (64 * VSTRIDE)    // 17408
#define SM_KH 0
#define SM_KL (2 * K_TILE_B)                    // 40960
#define SM_VH (4 * K_TILE_B)                    // 81920
#define SM_VL (4 * K_TILE_B + 2 * V_TILE_B)     // 116736
#define SM_TOTAL (4 * K_TILE_B + 4 * V_TILE_B)  // 151552

// ---------------- global scratch (allocation-free) ----------------
__device__ __half g_Qh[SEQ*DK], g_Ql[SEQ*DK];
__device__ __half g_Kh[SEQ*DK], g_Kl[SEQ*DK];
__device__ __half g_Vht[DV*SEQ], g_Vlt[DV*SEQ];   // V transposed [dv][seq]
__device__ float  g_Op[NSPLIT*SEQ*DV];            // unnormalized partial O
__device__ float  g_pm[NSPLIT*SEQ], g_pl[NSPLIT*SEQ];

// ---------------- helpers ----------------
__device__ __forceinline__ uint32_t smem_u32(const void* p){
    uint32_t a;
    asm("{ .reg .u64 t; cvta.to.shared.u64 t, %1; cvt.u32.u64 %0, t; }" : "=r"(a) : "l"(p));
    return a;
}
#define CP16(dst, src) asm volatile("cp.async.cg.shared.global [%0], [%1], 16;" :: "r"(dst), "l"(src) : "memory")
#define CP_COMMIT()    asm volatile("cp.async.commit_group;" ::: "memory")
#define CP_WAIT0()     asm volatile("cp.async.wait_group 0;" ::: "memory")

__device__ __forceinline__ void mma16816(float* c, const uint32_t* a, uint32_t b0, uint32_t b1){
    asm volatile("mma.sync.aligned.m16n8k16.row.col.f32.f16.f16.f32 "
        "{%0,%1,%2,%3}, {%4,%5,%6,%7}, {%8,%9}, {%0,%1,%2,%3};"
        : "+f"(c[0]), "+f"(c[1]), "+f"(c[2]), "+f"(c[3])
        : "r"(a[0]), "r"(a[1]), "r"(a[2]), "r"(a[3]), "r"(b0), "r"(b1));
}
__device__ __forceinline__ void ldsm4(uint32_t* r, uint32_t addr){
    asm volatile("ldmatrix.sync.aligned.m8n8.x4.shared.b16 {%0,%1,%2,%3}, [%4];"
        : "=r"(r[0]), "=r"(r[1]), "=r"(r[2]), "=r"(r[3]) : "r"(addr));
}
__device__ __forceinline__ uint32_t packh2(float lo, float hi){
    __half2 h = __floats2half2_rn(lo, hi);
    return reinterpret_cast<uint32_t&>(h);
}

// ---------------------------------------------------------------------------
// Kernel 1: fused QKV projection, fp32 SIMT; epilogue writes fp16 hi/lo splits.
// ---------------------------------------------------------------------------
__global__ __launch_bounds__(256, 1) void qkv_kernel(
    const float* __restrict__ x,
    const float* __restrict__ Wq,
    const float* __restrict__ Wk,
    const float* __restrict__ Wv)
{
    __shared__ float xs[64][68];
    __shared__ float ws[64][68];

    const float* W = (blockIdx.y == 0) ? Wq : (blockIdx.y == 1) ? Wk : Wv;

    const int tid = threadIdx.x;
    const int tx = tid & 15;
    const int ty = tid >> 4;
    const int m0 = blockIdx.x * 64;

    float acc[4][4] = {};

    for (int kt = 0; kt < DIM; kt += 64) {
        #pragma unroll
        for (int i = 0; i < 4; i++) {
            int f = i * 256 + tid;
            int row = f >> 4;
            int k4  = f & 15;
            float4 v = *(const float4*)(x + (size_t)(m0 + row) * DIM + kt + k4 * 4);
            xs[k4*4+0][row] = v.x; xs[k4*4+1][row] = v.y;
            xs[k4*4+2][row] = v.z; xs[k4*4+3][row] = v.w;
        }
        #pragma unroll
        for (int i = 0; i < 4; i++) {
            int f = i * 256 + tid;
            int k  = f >> 4;
            int n4 = f & 15;
            *(float4*)&ws[k][n4*4] = *(const float4*)(W + (size_t)(kt + k) * DK + n4 * 4);
        }
        __syncthreads();
        #pragma unroll 16
        for (int k = 0; k < 64; k++) {
            float4 a = *(float4*)&xs[k][ty*4];
            float4 b = *(float4*)&ws[k][tx*4];
            float av[4] = {a.x, a.y, a.z, a.w};
            float bv[4] = {b.x, b.y, b.z, b.w};
            #pragma unroll
            for (int r = 0; r < 4; r++)
                #pragma unroll
                for (int c = 0; c < 4; c++)
                    acc[r][c] = fmaf(av[r], bv[c], acc[r][c]);
        }
        __syncthreads();
    }

    if (blockIdx.y == 2) {
        // V: transposed scatter, hi/lo split
        #pragma unroll
        for (int r = 0; r < 4; r++)
            #pragma unroll
            for (int c = 0; c < 4; c++) {
                float v = acc[r][c];
                __half h = __float2half_rn(v);
                __half l = __float2half_rn(v - __half2float(h));
                int n = tx * 4 + c;
                int m = m0 + ty * 4 + r;
                g_Vht[(size_t)n * SEQ + m] = h;
                g_Vlt[(size_t)n * SEQ + m] = l;
            }
    } else {
        __half* Hp = blockIdx.y ? g_Kh : g_Qh;
        __half* Lp = blockIdx.y ? g_Kl : g_Ql;
        float sc = blockIdx.y ? 1.0f : 0.125f;   // fold 1/sqrt(64) into Q
        #pragma unroll
        for (int r = 0; r < 4; r++) {
            __half hh[4], ll[4];
            #pragma unroll
            for (int c = 0; c < 4; c++) {
                float v = acc[r][c] * sc;
                hh[c] = __float2half_rn(v);
                ll[c] = __float2half_rn(v - __half2float(hh[c]));
            }
            size_t base = (size_t)(m0 + ty*4 + r) * DK + tx * 4;
            *(__half2*)&Hp[base]   = __halves2half2(hh[0], hh[1]);
            *(__half2*)&Hp[base+2] = __halves2half2(hh[2], hh[3]);
            *(__half2*)&Lp[base]   = __halves2half2(ll[0], ll[1]);
            *(__half2*)&Lp[base+2] = __halves2half2(ll[2], ll[3]);
        }
    }
}

// ---------------------------------------------------------------------------
// smem loaders (cp.async 16B)
// ---------------------------------------------------------------------------
// K tile: 128 rows (n) x 64 halves (k), row stride KSTRIDE.
__device__ __forceinline__ void load_k(uint32_t dstbase, const __half* src, int n0, int tid){
    #pragma unroll
    for (int i = 0; i < 4; i++) {
        int f = i * 256 + tid;          // 1024 chunks
        int row = f >> 3, c = f & 7;
        CP16(dstbase + (uint32_t)(row * KSTRIDE + c * 16),
             src + (size_t)(n0 + row) * DK + c * 8);
    }
}
// V^T tile: 64 rows (dv) x 128 halves (kv), row stride VSTRIDE.
__device__ __forceinline__ void load_v(uint32_t dstbase, const __half* src, int k0, int tid){
    #pragma unroll
    for (int i = 0; i < 4; i++) {
        int f = i * 256 + tid;          // 1024 chunks
        int row = f >> 4, c = f & 15;
        CP16(dstbase + (uint32_t)(row * VSTRIDE + c * 16),
             src + (size_t)row * SEQ + k0 + c * 8);
    }
}

// ---------------------------------------------------------------------------
// Kernel 2: HMMA flash attention. grid = (SEQ/BM, NSPLIT), 256 threads.
// Warp w owns q-rows [w*16, w*16+16), full 128 KV cols -> warp-local softmax.
// ---------------------------------------------------------------------------
__global__ __launch_bounds__(256, 1) void flash_kernel()
{
    extern __shared__ char smem[];
    const uint32_t sb = smem_u32(smem);

    const int tid  = threadIdx.x;
    const int wid  = tid >> 5;
    const int lane = tid & 31;
    const int g    = lane >> 2;     // 0..7
    const int tig  = lane & 3;      // 0..3
    const int q0   = blockIdx.x * BM;
    const int split  = blockIdx.y;
    const int n_base = split * KV_PER;
    const int qrow = q0 + wid * 16;

    // ---- Q A-fragments (row-major), loaded once from gmem ----
    uint32_t aQh[4][4], aQl[4][4];
    #pragma unroll
    for (int ks = 0; ks < 4; ks++)
        #pragma unroll
        for (int i = 0; i < 4; i++) {
            int row = qrow + g + (i & 1) * 8;
            int col = 16 * ks + 2 * tig + (i >> 1) * 8;
            aQh[ks][i] = *(const uint32_t*)(g_Qh + (size_t)row * DK + col);
            aQl[ks][i] = *(const uint32_t*)(g_Ql + (size_t)row * DK + col);
        }

    // ---- prologue: tile 0 -> buf 0 ----
    load_k(sb + SM_KH, g_Kh, n_base, tid);
    load_k(sb + SM_KL, g_Kl, n_base, tid);
    load_v(sb + SM_VH, g_Vht, n_base, tid);
    load_v(sb + SM_VL, g_Vlt, n_base, tid);
    CP_COMMIT();

    float O[8][4];
    #pragma unroll
    for (int d = 0; d < 8; d++)
        #pragma unroll
        for (int j = 0; j < 4; j++) O[d][j] = 0.0f;
    float m_run[2] = {-1e30f, -1e30f};
    float l_run[2] = {0.0f, 0.0f};

    for (int t = 0; t < TILES; ++t) {
        CP_WAIT0();
        __syncthreads();

        const int buf = t & 1, nb = (t + 1) & 1;
        if (t + 1 < TILES) {
            int n1 = n_base + (t + 1) * BN;
            load_k(sb + SM_KH + nb * K_TILE_B, g_Kh, n1, tid);
            load_k(sb + SM_KL + nb * K_TILE_B, g_Kl, n1, tid);
            load_v(sb + SM_VH + nb * V_TILE_B, g_Vht, n1, tid);
            load_v(sb + SM_VL + nb * V_TILE_B, g_Vlt, n1, tid);
        }
        CP_COMMIT();

        // ---- S = Qh*Kh + Qh*Kl + Ql*Kh  (16 x 128 per warp) ----
        const uint32_t khb = sb + SM_KH + buf * K_TILE_B;
        const uint32_t klb = sb + SM_KL + buf * K_TILE_B;
        float c[16][4];
        #pragma unroll
        for (int nt = 0; nt < 16; nt++) {
            c[nt][0] = c[nt][1] = c[nt][2] = c[nt][3] = 0.0f;
            #pragma unroll
            for (int kp = 0; kp < 2; kp++) {
                uint32_t off = (uint32_t)((nt * 8 + (lane & 7)) * KSTRIDE
                                          + kp * 64 + (lane >> 3) * 16);
                uint32_t bh[4], bl[4];
                ldsm4(bh, khb + off);
                ldsm4(bl, klb + off);
                #pragma unroll
                for (int s = 0; s < 2; s++) {
                    int ks = kp * 2 + s;
                    mma16816(c[nt], aQh[ks], bh[2*s], bh[2*s+1]);
                    mma16816(c[nt], aQh[ks], bl[2*s], bl[2*s+1]);
                    mma16816(c[nt], aQl[ks], bh[2*s], bh[2*s+1]);
                }
            }
        }

        // ---- online softmax (warp-local; rows g and g+8) ----
        #pragma unroll
        for (int h = 0; h < 2; h++) {
            float mt = -1e30f;
            #pragma unroll
            for (int nt = 0; nt < 16; nt++)
                mt = fmaxf(mt, fmaxf(c[nt][2*h], c[nt][2*h+1]));
            mt = fmaxf(mt, __shfl_xor_sync(0xffffffffu, mt, 1));
            mt = fmaxf(mt, __shfl_xor_sync(0xffffffffu, mt, 2));
            float mnew  = fmaxf(m_run[h], mt);
            float alpha = __expf(m_run[h] - mnew);
            float sum = 0.0f;
            #pragma unroll
            for (int nt = 0; nt < 16; nt++) {
                float e0 = __expf(c[nt][2*h]   - mnew);
                float e1 = __expf(c[nt][2*h+1] - mnew);
                c[nt][2*h] = e0; c[nt][2*h+1] = e1;
                sum += e0 + e1;
            }
            sum += __shfl_xor_sync(0xffffffffu, sum, 1);
            sum += __shfl_xor_sync(0xffffffffu, sum, 2);
            m_run[h] = mnew;
            l_run[h] = l_run[h] * alpha + sum;
            #pragma unroll
            for (int d = 0; d < 8; d++) { O[d][2*h] *= alpha; O[d][2*h+1] *= alpha; }
        }

        // ---- pack P (S-frag -> A-frag reuse) ----
        uint32_t aP[8][4];
        #pragma unroll
        for (int k2 = 0; k2 < 8; k2++) {
            aP[k2][0] = packh2(c[2*k2][0],   c[2*k2][1]);
            aP[k2][1] = packh2(c[2*k2][2],   c[2*k2][3]);
            aP[k2][2] = packh2(c[2*k2+1][0], c[2*k2+1][1]);
            aP[k2][3] = packh2(c[2*k2+1][2], c[2*k2+1][3]);
        }

        // ---- O += P @ (Vh + Vl) ----
        const uint32_t vhb = sb + SM_VH + buf * V_TILE_B;
        const uint32_t vlb = sb + SM_VL + buf * V_TILE_B;
        #pragma unroll
        for (int dt = 0; dt < 8; dt++) {
            #pragma unroll
            for (int vp = 0; vp < 4; vp++) {
                uint32_t off = (uint32_t)((dt * 8 + (lane & 7)) * VSTRIDE
                                          + vp * 64 + (lane >> 3) * 16);
                uint32_t vh[4], vl[4];
                ldsm4(vh, vhb + off);
                ldsm4(vl, vlb + off);
                #pragma unroll
                for (int s = 0; s < 2; s++) {
                    int k2 = vp * 2 + s;
                    mma16816(O[dt], aP[k2], vh[2*s], vh[2*s+1]);
                    mma16816(O[dt], aP[k2], vl[2*s], vl[2*s+1]);
                }
            }
        }
    }

    // ---- epilogue: unnormalized partials + (m, l) ----
    #pragma unroll
    for (int h = 0; h < 2; h++) {
        int row = qrow + g + 8 * h;
        size_t rb = ((size_t)split * SEQ + row) * DV;
        #pragma unroll
        for (int dt = 0; dt < 8; dt++) {
            float2 v = make_float2(O[dt][2*h], O[dt][2*h+1]);
            *(float2*)&g_Op[rb + dt * 8 + 2 * tig] = v;
        }
        if (tig == 0) {
            g_pm[split * SEQ + row] = m_run[h];
            g_pl[split * SEQ + row] = l_run[h];
        }
    }
}

// ---------------------------------------------------------------------------
// Kernel 3: combine the two KV-split partials.
// ---------------------------------------------------------------------------
__global__ __launch_bounds__(256, 1) void combine_kernel(float* __restrict__ out)
{
    int idx = blockIdx.x * 256 + threadIdx.x;   // 0 .. SEQ*16-1
    int row = idx >> 4;
    int c4  = (idx & 15) * 4;
    float m0 = g_pm[row],      m1 = g_pm[SEQ + row];
    float M  = fmaxf(m0, m1);
    float w0 = __expf(m0 - M), w1 = __expf(m1 - M);
    float l  = w0 * g_pl[row] + w1 * g_pl[SEQ + row];
    float inv = 1.0f / l;
    float4 a = *(const float4*)&g_Op[(size_t)row * DV + c4];
    float4 b = *(const float4*)&g_Op[(size_t)(SEQ + row) * DV + c4];
    float4 o;
    o.x = (w0 * a.x + w1 * b.x) * inv;
    o.y = (w0 * a.y + w1 * b.y) * inv;
    o.z = (w0 * a.z + w1 * b.z) * inv;
    o.w = (w0 * a.w + w1 * b.w) * inv;
    *(float4*)&out[(size_t)row * DV + c4] = o;
}

// ---------------------------------------------------------------------------
extern "C" void kernel_launch(void* const* d_in, const int* in_sizes, int n_in,
                              void* d_out, int out_size)
{
    const float* x  = (const float*)d_in[0];
    const float* Wq = (const float*)d_in[1];
    const float* Wk = (const float*)d_in[2];
    const float* Wv = (const float*)d_in[3];
    float* out = (float*)d_out;

    dim3 g1(SEQ / 64, 3);
    qkv_kernel<<<g1, 256>>>(x, Wq, Wk, Wv);

    cudaFuncSetAttribute(flash_kernel,
                         cudaFuncAttributeMaxDynamicSharedMemorySize, SM_TOTAL);
    flash_kernel<<<dim3(SEQ / BM, NSPLIT), 256, SM_TOTAL>>>();

    combine_kernel<<<SEQ * 16 / 256, 256>>>(out);
}